// round 1
// baseline (speedup 1.0000x reference)
#include <cuda_runtime.h>
#include <cstddef>

// ---------------------------------------------------------------------------
// MultiHeadAttention: B=4, S=2048, D=256, H=8, HD=2048
// Pipeline:
//   1. Q/K/V projections: NT GEMM [8192,2048,256] + bias  -> g_q/g_k/g_v
//      (flat [B,S,HD] buffer == [B,H,S,D] view; no transpose needed)
//   2. scores = (1/16) * Q_h @ K_h^T : batched NT GEMM, 32 x [2048,2048,256]
//   3. row softmax over 2048
//   4. out = P @ V_h : batched NN GEMM, 32 x [2048,256,2048], written directly
//      into transposed [B,S,HD] layout via per-(b,h) column offset
//   5. y = out_t @ Wo^T + bo : NT GEMM [8192,256,2048] -> d_out
// ---------------------------------------------------------------------------

#define BM 64
#define BN 64
#define BK 16

static const int B_ = 4, S_ = 2048, D_ = 256, H_ = 8, HD_ = 2048;

// Scratch (allocation-free rule: __device__ globals)
__device__ float g_q[(size_t)4 * 2048 * 2048];   //  64 MB
__device__ float g_k[(size_t)4 * 2048 * 2048];   //  64 MB
__device__ float g_v[(size_t)4 * 2048 * 2048];   //  64 MB
__device__ float g_s[(size_t)32 * 2048 * 2048];  // 512 MB scores
__device__ float g_o[(size_t)4 * 2048 * 2048];   //  64 MB attn out (transposed layout)

// ---------------------------------------------------------------------------
// NT GEMM: C[M,N] = alpha * A[M,K] @ B[N,K]^T (+ bias[N])
// A, B both K-contiguous (lda/ldb along K). Batched via blockIdx.z with
// linear strides. Dims must be multiples of 64 (M,N) and 16 (K) — all are.
// ---------------------------------------------------------------------------
__global__ void __launch_bounds__(256) gemm_nt(
    const float* __restrict__ A, const float* __restrict__ B,
    const float* __restrict__ bias, float* __restrict__ C,
    int M, int N, int K, int lda, int ldb, int ldc, float alpha,
    long long sA, long long sB, long long sC)
{
    A += (long long)blockIdx.z * sA;
    B += (long long)blockIdx.z * sB;
    C += (long long)blockIdx.z * sC;

    __shared__ float As[BK][BM + 4];
    __shared__ float Bs[BK][BN + 4];

    const int tid  = threadIdx.x;
    const int row0 = blockIdx.y * BM;
    const int col0 = blockIdx.x * BN;
    const int lrow = tid >> 2;          // 0..63
    const int lk   = (tid & 3) << 2;    // 0,4,8,12
    const int ty   = tid >> 4;          // 0..15
    const int tx   = tid & 15;          // 0..15

    float acc[4][4] = {};

    for (int k0 = 0; k0 < K; k0 += BK) {
        float4 a = *(const float4*)(A + (size_t)(row0 + lrow) * lda + k0 + lk);
        float4 b = *(const float4*)(B + (size_t)(col0 + lrow) * ldb + k0 + lk);
        As[lk + 0][lrow] = a.x; As[lk + 1][lrow] = a.y;
        As[lk + 2][lrow] = a.z; As[lk + 3][lrow] = a.w;
        Bs[lk + 0][lrow] = b.x; Bs[lk + 1][lrow] = b.y;
        Bs[lk + 2][lrow] = b.z; Bs[lk + 3][lrow] = b.w;
        __syncthreads();
#pragma unroll
        for (int k = 0; k < BK; k++) {
            float ar[4], br[4];
#pragma unroll
            for (int i = 0; i < 4; i++) ar[i] = As[k][ty * 4 + i];
#pragma unroll
            for (int j = 0; j < 4; j++) br[j] = Bs[k][tx * 4 + j];
#pragma unroll
            for (int i = 0; i < 4; i++)
#pragma unroll
                for (int j = 0; j < 4; j++)
                    acc[i][j] = fmaf(ar[i], br[j], acc[i][j]);
        }
        __syncthreads();
    }

#pragma unroll
    for (int i = 0; i < 4; i++) {
        int r = row0 + ty * 4 + i;
#pragma unroll
        for (int j = 0; j < 4; j++) {
            int c = col0 + tx * 4 + j;
            float v = alpha * acc[i][j];
            if (bias) v += bias[c];
            C[(size_t)r * ldc + c] = v;
        }
    }
}

// ---------------------------------------------------------------------------
// NN GEMM: C = A[M,K] @ B[K,N]   (A K-contig, B N-contig)
// C offset per batch z: (z/Hp)*sC_b + (z%Hp)*sC_h  (for the head-transpose write)
// ---------------------------------------------------------------------------
__global__ void __launch_bounds__(256) gemm_nn(
    const float* __restrict__ A, const float* __restrict__ B,
    float* __restrict__ C,
    int M, int N, int K, int lda, int ldb, int ldc,
    long long sA, long long sB, int Hp, long long sC_b, long long sC_h)
{
    const int z = blockIdx.z;
    A += (long long)z * sA;
    B += (long long)z * sB;
    C += (long long)(z / Hp) * sC_b + (long long)(z % Hp) * sC_h;

    __shared__ float As[BK][BM + 4];
    __shared__ float Bs[BK][BN + 4];

    const int tid  = threadIdx.x;
    const int row0 = blockIdx.y * BM;
    const int col0 = blockIdx.x * BN;
    const int lrow = tid >> 2;          // A: 0..63
    const int lk   = (tid & 3) << 2;    // A: k offset
    const int lbk  = tid >> 4;          // B: 0..15 (k row)
    const int lbn  = (tid & 15) << 2;   // B: 0..60 (n col)
    const int ty   = tid >> 4;
    const int tx   = tid & 15;

    float acc[4][4] = {};

    for (int k0 = 0; k0 < K; k0 += BK) {
        float4 a = *(const float4*)(A + (size_t)(row0 + lrow) * lda + k0 + lk);
        float4 b = *(const float4*)(B + (size_t)(k0 + lbk) * ldb + col0 + lbn);
        As[lk + 0][lrow] = a.x; As[lk + 1][lrow] = a.y;
        As[lk + 2][lrow] = a.z; As[lk + 3][lrow] = a.w;
        Bs[lbk][lbn + 0] = b.x; Bs[lbk][lbn + 1] = b.y;
        Bs[lbk][lbn + 2] = b.z; Bs[lbk][lbn + 3] = b.w;
        __syncthreads();
#pragma unroll
        for (int k = 0; k < BK; k++) {
            float ar[4], br[4];
#pragma unroll
            for (int i = 0; i < 4; i++) ar[i] = As[k][ty * 4 + i];
#pragma unroll
            for (int j = 0; j < 4; j++) br[j] = Bs[k][tx * 4 + j];
#pragma unroll
            for (int i = 0; i < 4; i++)
#pragma unroll
                for (int j = 0; j < 4; j++)
                    acc[i][j] = fmaf(ar[i], br[j], acc[i][j]);
        }
        __syncthreads();
    }

#pragma unroll
    for (int i = 0; i < 4; i++) {
        int r = row0 + ty * 4 + i;
#pragma unroll
        for (int j = 0; j < 4; j++) {
            int c = col0 + tx * 4 + j;
            C[(size_t)r * ldc + c] = acc[i][j];
        }
    }
}

// ---------------------------------------------------------------------------
// Row softmax over fixed n=2048 (one block of 256 threads per row)
// ---------------------------------------------------------------------------
__global__ void __launch_bounds__(256) softmax_rows(float* __restrict__ s)
{
    const int n = 2048;
    float* row = s + (size_t)blockIdx.x * n;
    const int tid  = threadIdx.x;
    const int lane = tid & 31;
    const int wid  = tid >> 5;

    float4 v0 = ((const float4*)row)[tid];
    float4 v1 = ((const float4*)row)[tid + 256];

    float m = fmaxf(fmaxf(fmaxf(v0.x, v0.y), fmaxf(v0.z, v0.w)),
                    fmaxf(fmaxf(v1.x, v1.y), fmaxf(v1.z, v1.w)));

    __shared__ float smax[8];
    __shared__ float ssum[8];

#pragma unroll
    for (int o = 16; o > 0; o >>= 1) m = fmaxf(m, __shfl_xor_sync(0xffffffffu, m, o));
    if (lane == 0) smax[wid] = m;
    __syncthreads();
    if (tid < 32) {
        float mm = (tid < 8) ? smax[tid] : -3.4e38f;
#pragma unroll
        for (int o = 4; o > 0; o >>= 1) mm = fmaxf(mm, __shfl_xor_sync(0xffffffffu, mm, o));
        if (tid == 0) smax[0] = mm;
    }
    __syncthreads();
    m = smax[0];

    v0.x = expf(v0.x - m); v0.y = expf(v0.y - m);
    v0.z = expf(v0.z - m); v0.w = expf(v0.w - m);
    v1.x = expf(v1.x - m); v1.y = expf(v1.y - m);
    v1.z = expf(v1.z - m); v1.w = expf(v1.w - m);

    float sum = v0.x + v0.y + v0.z + v0.w + v1.x + v1.y + v1.z + v1.w;
#pragma unroll
    for (int o = 16; o > 0; o >>= 1) sum += __shfl_xor_sync(0xffffffffu, sum, o);
    if (lane == 0) ssum[wid] = sum;
    __syncthreads();
    if (tid < 32) {
        float ss = (tid < 8) ? ssum[tid] : 0.0f;
#pragma unroll
        for (int o = 4; o > 0; o >>= 1) ss += __shfl_xor_sync(0xffffffffu, ss, o);
        if (tid == 0) ssum[0] = ss;
    }
    __syncthreads();
    float inv = 1.0f / ssum[0];

    v0.x *= inv; v0.y *= inv; v0.z *= inv; v0.w *= inv;
    v1.x *= inv; v1.y *= inv; v1.z *= inv; v1.w *= inv;
    ((float4*)row)[tid]       = v0;
    ((float4*)row)[tid + 256] = v1;
}

// ---------------------------------------------------------------------------
extern "C" void kernel_launch(void* const* d_in, const int* in_sizes, int n_in,
                              void* d_out, int out_size)
{
    const float* query = (const float*)d_in[0];
    const float* key   = (const float*)d_in[1];
    const float* vals  = (const float*)d_in[2];
    const float* Wq    = (const float*)d_in[3];
    const float* bq    = (const float*)d_in[4];
    const float* Wk    = (const float*)d_in[5];
    const float* bk    = (const float*)d_in[6];
    const float* Wv    = (const float*)d_in[7];
    const float* bv    = (const float*)d_in[8];
    const float* Wo    = (const float*)d_in[9];
    const float* bo    = (const float*)d_in[10];
    float* out = (float*)d_out;

    float *q, *k, *v, *s, *o;
    cudaGetSymbolAddress((void**)&q, g_q);
    cudaGetSymbolAddress((void**)&k, g_k);
    cudaGetSymbolAddress((void**)&v, g_v);
    cudaGetSymbolAddress((void**)&s, g_s);
    cudaGetSymbolAddress((void**)&o, g_o);

    const int B = B_, S = S_, D = D_, H = H_, HD = HD_;
    dim3 blk(256);

    // 1. Projections: [B*S, HD] = in[B*S, D] @ W[HD, D]^T + b
    dim3 gp(HD / BN, (B * S) / BM, 1);
    gemm_nt<<<gp, blk>>>(query, Wq, bq, q, B * S, HD, D, D, D, HD, 1.0f, 0, 0, 0);
    gemm_nt<<<gp, blk>>>(key,   Wk, bk, k, B * S, HD, D, D, D, HD, 1.0f, 0, 0, 0);
    gemm_nt<<<gp, blk>>>(vals,  Wv, bv, v, B * S, HD, D, D, D, HD, 1.0f, 0, 0, 0);

    // 2. scores = (1/16) Q_h K_h^T : 32 batches of [S,S,D]
    dim3 gs(S / BN, S / BM, B * H);
    gemm_nt<<<gs, blk>>>(q, k, nullptr, s, S, S, D, D, D, S, 0.0625f,
                         (long long)S * D, (long long)S * D, (long long)S * S);

    // 3. softmax rows
    softmax_rows<<<B * H * S, 256>>>(s);

    // 4. out_t[b, s, h*D + d] = sum_k P[s,k] * V_h[k,d]
    dim3 gv(D / BN, S / BM, B * H);
    gemm_nn<<<gv, blk>>>(s, v, o, S, D, S, S, D, HD,
                         (long long)S * S, (long long)S * D,
                         H, (long long)S * HD, (long long)D);

    // 5. y = out_t @ Wo^T + bo : [8192, 256] , K = 2048
    dim3 gf(D / BN, (B * S) / BM, 1);
    gemm_nt<<<gf, blk>>>(o, Wo, bo, out, B * S, D, HD, HD, HD, D, 1.0f, 0, 0, 0);
}

// round 2
// speedup vs baseline: 2.5125x; 2.5125x over previous
#include <cuda_runtime.h>
#include <cstddef>

// ---------------------------------------------------------------------------
// MultiHeadAttention: B=4, S=2048, D=256, H=8, HD=2048
// All GEMMs on tensor pipe via mma.sync m16n8k8 tf32 (fp32 accumulate).
//   1. Q/K/V projections: NT [8192,2048,256] + bias
//   2. scores = (1/16) Q_h K_h^T : 32 x NT [2048,2048,256]
//   3. row softmax (n=2048)
//   4. out = P @ V_h : 32 x NN [2048,256,2048] -> transposed [B,S,HD] layout
//   5. y = out_t @ Wo^T + bo : NT [8192,256,2048]
// ---------------------------------------------------------------------------

#define BM 128
#define BN 128
#define BK 32
#define PAD 4

static const int B_ = 4, S_ = 2048, D_ = 256, H_ = 8, HD_ = 2048;

__device__ float g_q[(size_t)4 * 2048 * 2048];   //  64 MB
__device__ float g_k[(size_t)4 * 2048 * 2048];   //  64 MB
__device__ float g_v[(size_t)4 * 2048 * 2048];   //  64 MB
__device__ float g_s[(size_t)32 * 2048 * 2048];  // 512 MB scores
__device__ float g_o[(size_t)4 * 2048 * 2048];   //  64 MB

__device__ __forceinline__ unsigned f2tf(float f) {
    unsigned u;
    asm("cvt.rna.tf32.f32 %0, %1;" : "=r"(u) : "f"(f));
    return u;
}

__device__ __forceinline__ void mma_tf32(float c[4],
    unsigned a0, unsigned a1, unsigned a2, unsigned a3,
    unsigned b0, unsigned b1)
{
    asm volatile(
        "mma.sync.aligned.m16n8k8.row.col.f32.tf32.tf32.f32 "
        "{%0,%1,%2,%3}, {%4,%5,%6,%7}, {%8,%9}, {%0,%1,%2,%3};\n"
        : "+f"(c[0]), "+f"(c[1]), "+f"(c[2]), "+f"(c[3])
        : "r"(a0), "r"(a1), "r"(a2), "r"(a3), "r"(b0), "r"(b1));
}

// ---------------------------------------------------------------------------
// C[M,N] = alpha * A[M,K] @ op(B) (+ bias[N])
// BNT=true : B is [N,K], K-contiguous (NT)
// BNT=false: B is [K,N], N-contiguous (NN)
// Batched over blockIdx.z; C offset = (z/Hp)*sC_b + (z%Hp)*sC_h.
// M,N multiples of 128; K multiple of 32. (Holds for all 5 calls.)
// ---------------------------------------------------------------------------
template<bool BNT>
__global__ void __launch_bounds__(256) gemm_tc(
    const float* __restrict__ A, const float* __restrict__ B,
    const float* __restrict__ bias, float* __restrict__ C,
    int M, int N, int K, int lda, int ldb, int ldc, float alpha,
    long long sA, long long sB, int Hp, long long sC_b, long long sC_h)
{
    const int z = blockIdx.z;
    A += (long long)z * sA;
    B += (long long)z * sB;
    C += (long long)(z / Hp) * sC_b + (long long)(z % Hp) * sC_h;

    __shared__ unsigned As[BK][BM + PAD];
    __shared__ unsigned Bs[BK][BN + PAD];

    const int tid  = threadIdx.x;
    const int lane = tid & 31;
    const int warp = tid >> 5;
    const int g = lane >> 2;      // fragment group id (0..7)
    const int t = lane & 3;       // thread-in-group
    const int wm0 = (warp >> 2) * 64;   // warp row offset   (2 warps down)
    const int wn0 = (warp & 3) * 32;    // warp col offset   (4 warps across)
    const int row0 = blockIdx.y * BM;
    const int col0 = blockIdx.x * BN;

    const int arow = tid >> 3;          // 0..31 (M/N index for K-contig loads)
    const int acol = (tid & 7) << 2;    // 0..28 (k offset)
    const int bkr  = tid >> 5;          // 0..7   (k row, NN loads)
    const int bcol = (tid & 31) << 2;   // 0..124 (n offset, NN loads)

    float4 ar[4], br[4];

    float acc[4][4][4];
#pragma unroll
    for (int i = 0; i < 4; i++)
#pragma unroll
        for (int j = 0; j < 4; j++)
#pragma unroll
            for (int l = 0; l < 4; l++) acc[i][j][l] = 0.0f;

    // ---- prologue fetch ----
#pragma unroll
    for (int i = 0; i < 4; i++)
        ar[i] = *(const float4*)(A + (size_t)(row0 + arow + 32 * i) * lda + acol);
    if (BNT) {
#pragma unroll
        for (int i = 0; i < 4; i++)
            br[i] = *(const float4*)(B + (size_t)(col0 + arow + 32 * i) * ldb + acol);
    } else {
#pragma unroll
        for (int i = 0; i < 4; i++)
            br[i] = *(const float4*)(B + (size_t)(bkr + 8 * i) * ldb + col0 + bcol);
    }

    for (int k0 = 0; k0 < K; k0 += BK) {
        __syncthreads();
        // ---- stage to smem (k-major, converted to tf32) ----
#pragma unroll
        for (int i = 0; i < 4; i++) {
            int m = arow + 32 * i;
            As[acol + 0][m] = f2tf(ar[i].x);
            As[acol + 1][m] = f2tf(ar[i].y);
            As[acol + 2][m] = f2tf(ar[i].z);
            As[acol + 3][m] = f2tf(ar[i].w);
        }
        if (BNT) {
#pragma unroll
            for (int i = 0; i < 4; i++) {
                int n = arow + 32 * i;
                Bs[acol + 0][n] = f2tf(br[i].x);
                Bs[acol + 1][n] = f2tf(br[i].y);
                Bs[acol + 2][n] = f2tf(br[i].z);
                Bs[acol + 3][n] = f2tf(br[i].w);
            }
        } else {
#pragma unroll
            for (int i = 0; i < 4; i++) {
                int kk = bkr + 8 * i;
                Bs[kk][bcol + 0] = f2tf(br[i].x);
                Bs[kk][bcol + 1] = f2tf(br[i].y);
                Bs[kk][bcol + 2] = f2tf(br[i].z);
                Bs[kk][bcol + 3] = f2tf(br[i].w);
            }
        }
        __syncthreads();

        // ---- prefetch next tile while computing ----
        if (k0 + BK < K) {
#pragma unroll
            for (int i = 0; i < 4; i++)
                ar[i] = *(const float4*)(A + (size_t)(row0 + arow + 32 * i) * lda + k0 + BK + acol);
            if (BNT) {
#pragma unroll
                for (int i = 0; i < 4; i++)
                    br[i] = *(const float4*)(B + (size_t)(col0 + arow + 32 * i) * ldb + k0 + BK + acol);
            } else {
#pragma unroll
                for (int i = 0; i < 4; i++)
                    br[i] = *(const float4*)(B + (size_t)(k0 + BK + bkr + 8 * i) * ldb + col0 + bcol);
            }
        }

        // ---- compute: 4 k-steps of 8 ----
#pragma unroll
        for (int ks = 0; ks < BK; ks += 8) {
            unsigned af[4][4], bf[4][2];
#pragma unroll
            for (int mt = 0; mt < 4; mt++) {
                int m = wm0 + mt * 16 + g;
                af[mt][0] = As[ks + t][m];           // (row g,   col t)
                af[mt][1] = As[ks + t][m + 8];       // (row g+8, col t)
                af[mt][2] = As[ks + t + 4][m];       // (row g,   col t+4)
                af[mt][3] = As[ks + t + 4][m + 8];   // (row g+8, col t+4)
            }
#pragma unroll
            for (int nt = 0; nt < 4; nt++) {
                int n = wn0 + nt * 8 + g;
                bf[nt][0] = Bs[ks + t][n];           // (k t,   col g)
                bf[nt][1] = Bs[ks + t + 4][n];       // (k t+4, col g)
            }
#pragma unroll
            for (int mt = 0; mt < 4; mt++)
#pragma unroll
                for (int nt = 0; nt < 4; nt++)
                    mma_tf32(acc[mt][nt],
                             af[mt][0], af[mt][1], af[mt][2], af[mt][3],
                             bf[nt][0], bf[nt][1]);
        }
    }

    // ---- epilogue: c0:(g,2t) c1:(g,2t+1) c2:(g+8,2t) c3:(g+8,2t+1) ----
#pragma unroll
    for (int mt = 0; mt < 4; mt++) {
#pragma unroll
        for (int nt = 0; nt < 4; nt++) {
            int r = row0 + wm0 + mt * 16 + g;
            int c = col0 + wn0 + nt * 8 + 2 * t;
            float b0v = bias ? bias[c]     : 0.0f;
            float b1v = bias ? bias[c + 1] : 0.0f;
            float2 v0 = make_float2(fmaf(alpha, acc[mt][nt][0], b0v),
                                    fmaf(alpha, acc[mt][nt][1], b1v));
            float2 v1 = make_float2(fmaf(alpha, acc[mt][nt][2], b0v),
                                    fmaf(alpha, acc[mt][nt][3], b1v));
            *(float2*)(C + (size_t)r * ldc + c)       = v0;
            *(float2*)(C + (size_t)(r + 8) * ldc + c) = v1;
        }
    }
}

// ---------------------------------------------------------------------------
// Row softmax over fixed n=2048 (one block of 256 threads per row)
// ---------------------------------------------------------------------------
__global__ void __launch_bounds__(256) softmax_rows(float* __restrict__ s)
{
    const int n = 2048;
    float* row = s + (size_t)blockIdx.x * n;
    const int tid  = threadIdx.x;
    const int lane = tid & 31;
    const int wid  = tid >> 5;

    float4 v0 = ((const float4*)row)[tid];
    float4 v1 = ((const float4*)row)[tid + 256];

    float m = fmaxf(fmaxf(fmaxf(v0.x, v0.y), fmaxf(v0.z, v0.w)),
                    fmaxf(fmaxf(v1.x, v1.y), fmaxf(v1.z, v1.w)));

    __shared__ float smax[8];
    __shared__ float ssum[8];

#pragma unroll
    for (int o = 16; o > 0; o >>= 1) m = fmaxf(m, __shfl_xor_sync(0xffffffffu, m, o));
    if (lane == 0) smax[wid] = m;
    __syncthreads();
    if (tid < 32) {
        float mm = (tid < 8) ? smax[tid] : -3.4e38f;
#pragma unroll
        for (int o = 4; o > 0; o >>= 1) mm = fmaxf(mm, __shfl_xor_sync(0xffffffffu, mm, o));
        if (tid == 0) smax[0] = mm;
    }
    __syncthreads();
    m = smax[0];

    v0.x = expf(v0.x - m); v0.y = expf(v0.y - m);
    v0.z = expf(v0.z - m); v0.w = expf(v0.w - m);
    v1.x = expf(v1.x - m); v1.y = expf(v1.y - m);
    v1.z = expf(v1.z - m); v1.w = expf(v1.w - m);

    float sum = v0.x + v0.y + v0.z + v0.w + v1.x + v1.y + v1.z + v1.w;
#pragma unroll
    for (int o = 16; o > 0; o >>= 1) sum += __shfl_xor_sync(0xffffffffu, sum, o);
    if (lane == 0) ssum[wid] = sum;
    __syncthreads();
    if (tid < 32) {
        float ss = (tid < 8) ? ssum[tid] : 0.0f;
#pragma unroll
        for (int o = 4; o > 0; o >>= 1) ss += __shfl_xor_sync(0xffffffffu, ss, o);
        if (tid == 0) ssum[0] = ss;
    }
    __syncthreads();
    float inv = 1.0f / ssum[0];

    v0.x *= inv; v0.y *= inv; v0.z *= inv; v0.w *= inv;
    v1.x *= inv; v1.y *= inv; v1.z *= inv; v1.w *= inv;
    ((float4*)row)[tid]       = v0;
    ((float4*)row)[tid + 256] = v1;
}

// ---------------------------------------------------------------------------
extern "C" void kernel_launch(void* const* d_in, const int* in_sizes, int n_in,
                              void* d_out, int out_size)
{
    const float* query = (const float*)d_in[0];
    const float* key   = (const float*)d_in[1];
    const float* vals  = (const float*)d_in[2];
    const float* Wq    = (const float*)d_in[3];
    const float* bq    = (const float*)d_in[4];
    const float* Wk    = (const float*)d_in[5];
    const float* bk    = (const float*)d_in[6];
    const float* Wv    = (const float*)d_in[7];
    const float* bv    = (const float*)d_in[8];
    const float* Wo    = (const float*)d_in[9];
    const float* bo    = (const float*)d_in[10];
    float* out = (float*)d_out;

    float *q, *k, *v, *s, *o;
    cudaGetSymbolAddress((void**)&q, g_q);
    cudaGetSymbolAddress((void**)&k, g_k);
    cudaGetSymbolAddress((void**)&v, g_v);
    cudaGetSymbolAddress((void**)&s, g_s);
    cudaGetSymbolAddress((void**)&o, g_o);

    const int B = B_, S = S_, D = D_, H = H_, HD = HD_;
    dim3 blk(256);

    // 1. Projections: [8192, 2048] = in @ W^T + b   (K=256)
    dim3 gp(HD / BN, (B * S) / BM, 1);
    gemm_tc<true><<<gp, blk>>>(query, Wq, bq, q, B * S, HD, D, D, D, HD, 1.0f,
                               0, 0, 1, 0, 0);
    gemm_tc<true><<<gp, blk>>>(key,   Wk, bk, k, B * S, HD, D, D, D, HD, 1.0f,
                               0, 0, 1, 0, 0);
    gemm_tc<true><<<gp, blk>>>(vals,  Wv, bv, v, B * S, HD, D, D, D, HD, 1.0f,
                               0, 0, 1, 0, 0);

    // 2. scores = (1/16) Q_h K_h^T : 32 x [2048,2048,256]
    dim3 gs(S / BN, S / BM, B * H);
    gemm_tc<true><<<gs, blk>>>(q, k, nullptr, s, S, S, D, D, D, S, 0.0625f,
                               (long long)S * D, (long long)S * D,
                               1, (long long)S * S, 0);

    // 3. softmax rows
    softmax_rows<<<B * H * S, 256>>>(s);

    // 4. out_t[b, s, h*D + d] = P @ V_h : 32 x [2048,256,2048]
    dim3 gv(D / BN, S / BM, B * H);
    gemm_tc<false><<<gv, blk>>>(s, v, nullptr, o, S, D, S, S, D, HD, 1.0f,
                                (long long)S * S, (long long)S * D,
                                H, (long long)S * HD, (long long)D);

    // 5. y = out_t @ Wo^T + bo : [8192,256,2048]
    dim3 gf(D / BN, (B * S) / BM, 1);
    gemm_tc<true><<<gf, blk>>>(o, Wo, bo, out, B * S, D, HD, HD, HD, D, 1.0f,
                               0, 0, 1, 0, 0);
}

// round 4
// speedup vs baseline: 3.9438x; 1.5697x over previous
#include <cuda_runtime.h>
#include <cstdint>
#include <cstddef>

// ---------------------------------------------------------------------------
// MultiHeadAttention: B=4, S=2048, D=256, H=8, HD=2048
// All GEMMs via mma.sync m16n8k8 tf32 (raw-fp32 operands, HW-truncated),
// cp.async double-buffered smem, 4 warps x 64x64 warp tiles (128x128 block).
//   1. Q/K/V projections: NT [8192,2048,256] + bias
//   2. scores = (1/16) Q_h K_h^T : 32 x NT [2048,2048,256]
//   3. row softmax (n=2048)
//   4. out = P @ V_h : 32 x NN [2048,256,2048] -> transposed [B,S,HD] layout
//   5. y = out_t @ Wo^T + bo : NT [8192,256,2048]
// ---------------------------------------------------------------------------

static const int B_ = 4, S_ = 2048, D_ = 256, H_ = 8, HD_ = 2048;

__device__ float g_q[(size_t)4 * 2048 * 2048];    //  64 MB
__device__ float g_k[(size_t)4 * 2048 * 2048];    //  64 MB
__device__ float g_v[(size_t)4 * 2048 * 2048];    //  64 MB
__device__ float g_s[(size_t)32 * 2048 * 2048];   // 512 MB scores
__device__ float g_o[(size_t)4 * 2048 * 2048];    //  64 MB

// A / NT-B smem tile: [128 rows][36 floats]  (32 k + 4 pad) = 18432 B
// NN-B smem tile:     [32 k rows][136 floats] (128 n + 8 pad) = 17408 B (slot 18432)
#define RA 36
#define RB 136
#define OP_BYTES   18432
#define STAGE_BYTES (2 * OP_BYTES)
#define GEMM_SMEM  (2 * STAGE_BYTES)          // 73728

__device__ __forceinline__ uint32_t smem_u32(const void* p) {
    uint32_t a;
    asm("{ .reg .u64 t; cvta.to.shared.u64 t, %1; cvt.u32.u64 %0, t; }"
        : "=r"(a) : "l"(p));
    return a;
}

__device__ __forceinline__ void cp_async16(uint32_t saddr, const void* g) {
    asm volatile("cp.async.cg.shared.global [%0], [%1], 16;" :: "r"(saddr), "l"(g));
}

__device__ __forceinline__ void mma_tf32(float c[4],
    uint32_t a0, uint32_t a1, uint32_t a2, uint32_t a3,
    uint32_t b0, uint32_t b1)
{
    asm volatile(
        "mma.sync.aligned.m16n8k8.row.col.f32.tf32.tf32.f32 "
        "{%0,%1,%2,%3}, {%4,%5,%6,%7}, {%8,%9}, {%0,%1,%2,%3};\n"
        : "+f"(c[0]), "+f"(c[1]), "+f"(c[2]), "+f"(c[3])
        : "r"(a0), "r"(a1), "r"(a2), "r"(a3), "r"(b0), "r"(b1));
}

// ---------------------------------------------------------------------------
// C[128y,128x] = alpha * A[M,K] @ op(B) (+ bias)
// BNT=true : B is [N,K] K-contiguous.  BNT=false: B is [K,N] N-contiguous.
// K multiple of 32. Batched over z; C offset (z/Hp)*sC_b + (z%Hp)*sC_h.
// ---------------------------------------------------------------------------
template<bool BNT>
__global__ void __launch_bounds__(128, 2) gemm_ws(
    const float* __restrict__ A, const float* __restrict__ B,
    const float* __restrict__ bias, float* __restrict__ C,
    int K, int lda, int ldb, int ldc, float alpha,
    long long sA, long long sB, int Hp, long long sC_b, long long sC_h)
{
    extern __shared__ __align__(16) float smem[];
    const uint32_t sbase = smem_u32(smem);

    const int tid  = threadIdx.x;
    const int lane = tid & 31;
    const int warp = tid >> 5;
    const int g = lane >> 2;
    const int t = lane & 3;
    const int wm0 = (warp >> 1) * 64;
    const int wn0 = (warp & 1) * 64;

    const int z = blockIdx.z;
    A += (long long)z * sA + (size_t)blockIdx.y * 128 * lda;
    B += (long long)z * sB;
    if (BNT) B += (size_t)blockIdx.x * 128 * ldb;
    else     B += (size_t)blockIdx.x * 128;
    C += (long long)(z / Hp) * sC_b + (long long)(z % Hp) * sC_h;
    const int row0 = blockIdx.y * 128;
    const int col0 = blockIdx.x * 128;

    const int nch = K >> 5;

    // staging decomposition
    const int ar = tid >> 3;        // 0..15 step -> rows r, r+16, ... (8 iters cover 128)
    const int ac = tid & 7;         // 16B chunk within 32-k row
    const int bkr = tid >> 5;       // NN: k row 0..3 (+4 per iter)
    const int bnc = tid & 31;       // NN: 16B chunk within 128-n row

    auto stage = [&](int chunk, int buf) {
        const uint32_t abuf = sbase + buf * STAGE_BYTES;
        const uint32_t bbuf = abuf + OP_BYTES;
        const float* Ak = A + chunk * 32;
#pragma unroll
        for (int i = 0; i < 8; i++) {
            int r = ar + i * 16;
            cp_async16(abuf + r * (RA * 4) + ac * 16,
                       Ak + (size_t)r * lda + ac * 4);
        }
        if (BNT) {
            const float* Bk = B + chunk * 32;
#pragma unroll
            for (int i = 0; i < 8; i++) {
                int r = ar + i * 16;
                cp_async16(bbuf + r * (RA * 4) + ac * 16,
                           Bk + (size_t)r * ldb + ac * 4);
            }
        } else {
            const float* Bk = B + (size_t)chunk * 32 * ldb;
#pragma unroll
            for (int i = 0; i < 8; i++) {
                int kr = bkr + i * 4;
                cp_async16(bbuf + kr * (RB * 4) + bnc * 16,
                           Bk + (size_t)kr * ldb + bnc * 4);
            }
        }
        asm volatile("cp.async.commit_group;" ::: "memory");
    };

    float acc[4][8][4];
#pragma unroll
    for (int i = 0; i < 4; i++)
#pragma unroll
        for (int j = 0; j < 8; j++)
#pragma unroll
            for (int l = 0; l < 4; l++) acc[i][j][l] = 0.0f;

    stage(0, 0);

    for (int i = 0; i < nch; i++) {
        if (i + 1 < nch) {
            stage(i + 1, (i + 1) & 1);
            asm volatile("cp.async.wait_group 1;" ::: "memory");
        } else {
            asm volatile("cp.async.wait_group 0;" ::: "memory");
        }
        __syncthreads();

        const float* As = smem + (i & 1) * (STAGE_BYTES / 4);
        const float* Bs = As + OP_BYTES / 4;

#pragma unroll
        for (int ks = 0; ks < 32; ks += 8) {
            uint32_t af[4][4], bf[8][2];
#pragma unroll
            for (int mt = 0; mt < 4; mt++) {
                const float* ap = As + (wm0 + mt * 16 + g) * RA + ks + t;
                af[mt][0] = __float_as_uint(ap[0]);
                af[mt][1] = __float_as_uint(ap[8 * RA]);
                af[mt][2] = __float_as_uint(ap[4]);
                af[mt][3] = __float_as_uint(ap[8 * RA + 4]);
            }
            if (BNT) {
#pragma unroll
                for (int nt = 0; nt < 8; nt++) {
                    const float* bp = Bs + (wn0 + nt * 8 + g) * RA + ks + t;
                    bf[nt][0] = __float_as_uint(bp[0]);
                    bf[nt][1] = __float_as_uint(bp[4]);
                }
            } else {
#pragma unroll
                for (int nt = 0; nt < 8; nt++) {
                    const float* bp = Bs + (ks + t) * RB + wn0 + nt * 8 + g;
                    bf[nt][0] = __float_as_uint(bp[0]);
                    bf[nt][1] = __float_as_uint(bp[4 * RB]);
                }
            }
#pragma unroll
            for (int mt = 0; mt < 4; mt++)
#pragma unroll
                for (int nt = 0; nt < 8; nt++)
                    mma_tf32(acc[mt][nt],
                             af[mt][0], af[mt][1], af[mt][2], af[mt][3],
                             bf[nt][0], bf[nt][1]);
        }
        __syncthreads();
    }

    // epilogue: c0:(g,2t) c1:(g,2t+1) c2:(g+8,2t) c3:(g+8,2t+1)
#pragma unroll
    for (int mt = 0; mt < 4; mt++) {
#pragma unroll
        for (int nt = 0; nt < 8; nt++) {
            int r = row0 + wm0 + mt * 16 + g;
            int c = col0 + wn0 + nt * 8 + 2 * t;
            float b0v = bias ? bias[c]     : 0.0f;
            float b1v = bias ? bias[c + 1] : 0.0f;
            float2 v0 = make_float2(fmaf(alpha, acc[mt][nt][0], b0v),
                                    fmaf(alpha, acc[mt][nt][1], b1v));
            float2 v1 = make_float2(fmaf(alpha, acc[mt][nt][2], b0v),
                                    fmaf(alpha, acc[mt][nt][3], b1v));
            *(float2*)(C + (size_t)r * ldc + c)       = v0;
            *(float2*)(C + (size_t)(r + 8) * ldc + c) = v1;
        }
    }
}

// ---------------------------------------------------------------------------
// Row softmax over fixed n=2048 (one block of 256 threads per row)
// ---------------------------------------------------------------------------
__global__ void __launch_bounds__(256) softmax_rows(float* __restrict__ s)
{
    const int n = 2048;
    float* row = s + (size_t)blockIdx.x * n;
    const int tid  = threadIdx.x;
    const int lane = tid & 31;
    const int wd   = tid >> 5;

    float4 v0 = ((const float4*)row)[tid];
    float4 v1 = ((const float4*)row)[tid + 256];

    float m = fmaxf(fmaxf(fmaxf(v0.x, v0.y), fmaxf(v0.z, v0.w)),
                    fmaxf(fmaxf(v1.x, v1.y), fmaxf(v1.z, v1.w)));

    __shared__ float smax[8];
    __shared__ float ssum[8];

#pragma unroll
    for (int o = 16; o > 0; o >>= 1) m = fmaxf(m, __shfl_xor_sync(0xffffffffu, m, o));
    if (lane == 0) smax[wd] = m;
    __syncthreads();
    if (tid < 32) {
        float mm = (tid < 8) ? smax[tid] : -3.4e38f;
#pragma unroll
        for (int o = 4; o > 0; o >>= 1) mm = fmaxf(mm, __shfl_xor_sync(0xffffffffu, mm, o));
        if (tid == 0) smax[0] = mm;
    }
    __syncthreads();
    m = smax[0];

    v0.x = expf(v0.x - m); v0.y = expf(v0.y - m);
    v0.z = expf(v0.z - m); v0.w = expf(v0.w - m);
    v1.x = expf(v1.x - m); v1.y = expf(v1.y - m);
    v1.z = expf(v1.z - m); v1.w = expf(v1.w - m);

    float sum = v0.x + v0.y + v0.z + v0.w + v1.x + v1.y + v1.z + v1.w;
#pragma unroll
    for (int o = 16; o > 0; o >>= 1) sum += __shfl_xor_sync(0xffffffffu, sum, o);
    if (lane == 0) ssum[wd] = sum;
    __syncthreads();
    if (tid < 32) {
        float ss = (tid < 8) ? ssum[tid] : 0.0f;
#pragma unroll
        for (int o = 4; o > 0; o >>= 1) ss += __shfl_xor_sync(0xffffffffu, ss, o);
        if (tid == 0) ssum[0] = ss;
    }
    __syncthreads();
    float inv = 1.0f / ssum[0];

    v0.x *= inv; v0.y *= inv; v0.z *= inv; v0.w *= inv;
    v1.x *= inv; v1.y *= inv; v1.z *= inv; v1.w *= inv;
    ((float4*)row)[tid]       = v0;
    ((float4*)row)[tid + 256] = v1;
}

// ---------------------------------------------------------------------------
extern "C" void kernel_launch(void* const* d_in, const int* in_sizes, int n_in,
                              void* d_out, int out_size)
{
    const float* query = (const float*)d_in[0];
    const float* key   = (const float*)d_in[1];
    const float* vals  = (const float*)d_in[2];
    const float* Wq    = (const float*)d_in[3];
    const float* bq    = (const float*)d_in[4];
    const float* Wk    = (const float*)d_in[5];
    const float* bk    = (const float*)d_in[6];
    const float* Wv    = (const float*)d_in[7];
    const float* bv    = (const float*)d_in[8];
    const float* Wo    = (const float*)d_in[9];
    const float* bo    = (const float*)d_in[10];
    float* out = (float*)d_out;

    float *q, *k, *v, *s, *o;
    cudaGetSymbolAddress((void**)&q, g_q);
    cudaGetSymbolAddress((void**)&k, g_k);
    cudaGetSymbolAddress((void**)&v, g_v);
    cudaGetSymbolAddress((void**)&s, g_s);
    cudaGetSymbolAddress((void**)&o, g_o);

    cudaFuncSetAttribute(gemm_ws<true>,
                         cudaFuncAttributeMaxDynamicSharedMemorySize, GEMM_SMEM);
    cudaFuncSetAttribute(gemm_ws<false>,
                         cudaFuncAttributeMaxDynamicSharedMemorySize, GEMM_SMEM);

    const int B = B_, S = S_, D = D_, H = H_, HD = HD_;
    dim3 blk(128);
    size_t sm = GEMM_SMEM;

    // 1. Projections: [8192,2048] = in @ W^T + b   (K=256)
    dim3 gp(HD / 128, (B * S) / 128, 1);
    gemm_ws<true><<<gp, blk, sm>>>(query, Wq, bq, q, D, D, D, HD, 1.0f, 0, 0, 1, 0, 0);
    gemm_ws<true><<<gp, blk, sm>>>(key,   Wk, bk, k, D, D, D, HD, 1.0f, 0, 0, 1, 0, 0);
    gemm_ws<true><<<gp, blk, sm>>>(vals,  Wv, bv, v, D, D, D, HD, 1.0f, 0, 0, 1, 0, 0);

    // 2. scores = (1/16) Q_h K_h^T : 32 x [2048,2048,256]
    //    head h of batch b = contiguous [2048,256] chunk (raw-reshape property)
    dim3 gs(S / 128, S / 128, B * H);
    gemm_ws<true><<<gs, blk, sm>>>(q, k, nullptr, s, D, D, D, S, 0.0625f,
                                   (long long)S * D, (long long)S * D,
                                   1, (long long)S * S, 0);

    // 3. softmax rows
    softmax_rows<<<B * H * S, 256>>>(s);

    // 4. out_t[b, s, h*D + d] = P @ V_h : 32 x NN [2048,256,2048]
    dim3 gv(D / 128, S / 128, B * H);
    gemm_ws<false><<<gv, blk, sm>>>(s, v, nullptr, o, S, S, D, HD, 1.0f,
                                    (long long)S * S, (long long)S * D,
                                    H, (long long)S * HD, (long long)D);

    // 5. y = out_t @ Wo^T + bo : [8192,256,2048]
    dim3 gf(D / 128, (B * S) / 128, 1);
    gemm_ws<true><<<gf, blk, sm>>>(o, Wo, bo, out, HD, HD, HD, D, 1.0f,
                                   0, 0, 1, 0, 0);
}